// round 1
// baseline (speedup 1.0000x reference)
#include <cuda_runtime.h>
#include <cstdint>

#define N_NODES 100000
#define N_EDGES 1200000
#define D_FEAT  64
#define CHUNKS  16              // 64 floats = 16 float4 per row

// THETA = (1.0, -0.8, 0.4, -0.1)
#define THETA0  1.0f
#define THETA1 -0.8f
#define THETA2  0.4f
#define THETA3 -0.1f

// ---------------- scratch (static device memory; no allocs allowed) --------
__device__ int   g_deg [N_NODES];
__device__ float g_dinv[N_NODES];
__device__ float g_feat[(size_t)N_NODES * D_FEAT];
__device__ float g_agg [(size_t)N_NODES * D_FEAT];

// ---------------- kernels ---------------------------------------------------

__global__ void zero_deg_kernel() {
    int v = blockIdx.x * blockDim.x + threadIdx.x;
    if (v < N_NODES) g_deg[v] = 0;
}

__global__ void deg_kernel(const int* __restrict__ dst) {
    int e = blockIdx.x * blockDim.x + threadIdx.x;
    if (e < N_EDGES) atomicAdd(&g_deg[__ldg(dst + e)], 1);
}

__global__ void dinv_kernel() {
    int v = blockIdx.x * blockDim.x + threadIdx.x;
    if (v < N_NODES) {
        float d = (float)g_deg[v];
        g_dinv[v] = rsqrtf(fmaxf(d, 1.0f));
    }
}

// Copy feat -> g_feat, out = theta0 * feat, agg = 0. One float4 per thread.
__global__ void init_kernel(const float* __restrict__ feat, float* __restrict__ out) {
    int gid = blockIdx.x * blockDim.x + threadIdx.x;
    if (gid >= N_NODES * CHUNKS) return;
    float4 f = ((const float4*)feat)[gid];
    ((float4*)g_feat)[gid] = f;
    float4 o = make_float4(THETA0 * f.x, THETA0 * f.y, THETA0 * f.z, THETA0 * f.w);
    ((float4*)out)[gid] = o;
    ((float4*)g_agg)[gid] = make_float4(0.f, 0.f, 0.f, 0.f);
}

// Edge scatter: agg[dst] += feat[src] * dinv[src].
// 16 consecutive threads handle one edge (one float4 each) -> coalesced 256B
// row read; vectorized red.global.add.v4.f32 scatter (no return value).
__global__ void scatter_kernel(const int* __restrict__ src,
                               const int* __restrict__ dst) {
    int gid = blockIdx.x * blockDim.x + threadIdx.x;
    if (gid >= N_EDGES * CHUNKS) return;
    int e = gid >> 4;
    int c = gid & 15;
    int s = __ldg(src + e);
    int d = __ldg(dst + e);
    float ds = __ldg(&g_dinv[s]);
    float4 f = ((const float4*)(g_feat + (size_t)s * D_FEAT))[c];
    float mx = f.x * ds, my = f.y * ds, mz = f.z * ds, mw = f.w * ds;
    float* p = g_agg + (size_t)d * D_FEAT + c * 4;
    asm volatile("red.global.add.v4.f32 [%0], {%1, %2, %3, %4};"
                 :: "l"(p), "f"(mx), "f"(my), "f"(mz), "f"(mw)
                 : "memory");
}

// Node update: feat = feat - agg * dinv; out += theta * feat; agg = 0 (for next iter).
__global__ void update_kernel(float* __restrict__ out, float theta) {
    int gid = blockIdx.x * blockDim.x + threadIdx.x;
    if (gid >= N_NODES * CHUNKS) return;
    int v = gid >> 4;
    float dv = __ldg(&g_dinv[v]);
    float4 a = ((float4*)g_agg)[gid];
    float4 f = ((float4*)g_feat)[gid];
    f.x -= a.x * dv;  f.y -= a.y * dv;  f.z -= a.z * dv;  f.w -= a.w * dv;
    ((float4*)g_feat)[gid] = f;
    float4 o = ((float4*)out)[gid];
    o.x += theta * f.x;  o.y += theta * f.y;  o.z += theta * f.z;  o.w += theta * f.w;
    ((float4*)out)[gid] = o;
    ((float4*)g_agg)[gid] = make_float4(0.f, 0.f, 0.f, 0.f);
}

// ---------------- launch -----------------------------------------------------

extern "C" void kernel_launch(void* const* d_in, const int* in_sizes, int n_in,
                              void* d_out, int out_size) {
    const float* feat = (const float*)d_in[0];
    const int*   src  = (const int*)d_in[1];
    const int*   dst  = (const int*)d_in[2];
    float* out = (float*)d_out;

    const int T = 256;
    const int node_elems = N_NODES * CHUNKS;   // 1.6M float4
    const int edge_elems = N_EDGES * CHUNKS;   // 19.2M threads

    zero_deg_kernel<<<(N_NODES + T - 1) / T, T>>>();
    deg_kernel<<<(N_EDGES + T - 1) / T, T>>>(dst);
    dinv_kernel<<<(N_NODES + T - 1) / T, T>>>();
    init_kernel<<<(node_elems + T - 1) / T, T>>>(feat, out);

    const float thetas[3] = {THETA1, THETA2, THETA3};
    for (int k = 0; k < 3; ++k) {
        scatter_kernel<<<(edge_elems + T - 1) / T, T>>>(src, dst);
        update_kernel<<<(node_elems + T - 1) / T, T>>>(out, thetas[k]);
    }
}